// round 15
// baseline (speedup 1.0000x reference)
#include <cuda_runtime.h>
#include <cuda_bf16.h>
#include <cstdint>
#include <math.h>

#define B_   2
#define S_   2048
#define E_   1024
#define H_   16
#define D_   64
#define MTOT (B_ * S_)   // 4096
#define ROWS_TOT (B_ * H_ * S_)   // 65536 attention rows

// ---- prepacked bf16 scratch (hi/lo split), __device__ globals ----
__device__ __nv_bfloat16 g_inq_h[MTOT * E_], g_inq_l[MTOT * E_];
__device__ __nv_bfloat16 g_ink_h[MTOT * E_], g_ink_l[MTOT * E_];
__device__ __nv_bfloat16 g_inv_h[MTOT * E_], g_inv_l[MTOT * E_];
__device__ __nv_bfloat16 g_win_h[3 * E_ * E_], g_win_l[3 * E_ * E_];
__device__ __nv_bfloat16 g_wout_h[E_ * E_], g_wout_l[E_ * E_];
__device__ __nv_bfloat16 g_pq_h[MTOT * E_], g_pq_l[MTOT * E_];
__device__ __nv_bfloat16 g_pk_h[MTOT * E_], g_pk_l[MTOT * E_];
__device__ __nv_bfloat16 g_pv_h[MTOT * E_], g_pv_l[MTOT * E_];
__device__ __nv_bfloat16 g_at_h[MTOT * E_], g_at_l[MTOT * E_];
// split-KV partials: [half][b][h][s][64] fp32 + per-row m,l
__device__ float g_po[2 * ROWS_TOT * D_];
__device__ float g_pm[2 * ROWS_TOT];
__device__ float g_pl[2 * ROWS_TOT];

__device__ __forceinline__ uint32_t smem_u32(const void* p) {
    uint32_t a;
    asm("{ .reg .u64 t; cvta.to.shared.u64 t, %1; cvt.u32.u64 %0, t; }"
        : "=r"(a) : "l"(p));
    return a;
}

#define SWZ128(off) ((off) ^ (((off) >> 3) & 0x70))

__device__ __forceinline__ void cp_async16(uint32_t dst, const void* src) {
    asm volatile("cp.async.cg.shared.global [%0], [%1], 16;"
                 :: "r"(dst), "l"(src));
}
#define CP_COMMIT() asm volatile("cp.async.commit_group;" ::: "memory")
#define CP_WAIT(n)  asm volatile("cp.async.wait_group %0;" :: "n"(n) : "memory")

__device__ __forceinline__ void ldsm_x4(uint32_t addr, uint32_t* r) {
    asm volatile(
        "ldmatrix.sync.aligned.m8n8.x4.shared.b16 {%0,%1,%2,%3}, [%4];"
        : "=r"(r[0]), "=r"(r[1]), "=r"(r[2]), "=r"(r[3]) : "r"(addr));
}
__device__ __forceinline__ void ldsm_x4_t(uint32_t addr, uint32_t* r) {
    asm volatile(
        "ldmatrix.sync.aligned.m8n8.x4.trans.shared.b16 {%0,%1,%2,%3}, [%4];"
        : "=r"(r[0]), "=r"(r[1]), "=r"(r[2]), "=r"(r[3]) : "r"(addr));
}
__device__ __forceinline__ void mma16816(float* d, const uint32_t* a, const uint32_t* b) {
    asm volatile(
        "mma.sync.aligned.m16n8k16.row.col.f32.bf16.bf16.f32 "
        "{%0,%1,%2,%3}, {%4,%5,%6,%7}, {%8,%9}, {%0,%1,%2,%3};"
        : "+f"(d[0]), "+f"(d[1]), "+f"(d[2]), "+f"(d[3])
        : "r"(a[0]), "r"(a[1]), "r"(a[2]), "r"(a[3]), "r"(b[0]), "r"(b[1]));
}

__device__ __forceinline__ void split4(float4 v, uint2& h, uint2& l)
{
    __nv_bfloat162 h01 = __floats2bfloat162_rn(v.x, v.y);
    __nv_bfloat162 h23 = __floats2bfloat162_rn(v.z, v.w);
    float2 f01 = __bfloat1622float2(h01);
    float2 f23 = __bfloat1622float2(h23);
    __nv_bfloat162 l01 = __floats2bfloat162_rn(v.x - f01.x, v.y - f01.y);
    __nv_bfloat162 l23 = __floats2bfloat162_rn(v.z - f23.x, v.w - f23.y);
    h.x = *reinterpret_cast<uint32_t*>(&h01);
    h.y = *reinterpret_cast<uint32_t*>(&h23);
    l.x = *reinterpret_cast<uint32_t*>(&l01);
    l.y = *reinterpret_cast<uint32_t*>(&l23);
}
__device__ __forceinline__ void split2(float a, float b, uint32_t& hi, uint32_t& lo)
{
    __nv_bfloat162 h = __floats2bfloat162_rn(a, b);
    float2 f = __bfloat1622float2(h);
    __nv_bfloat162 l = __floats2bfloat162_rn(a - f.x, b - f.y);
    hi = *reinterpret_cast<uint32_t*>(&h);
    lo = *reinterpret_cast<uint32_t*>(&l);
}

// ===========================================================================
// Prepack: all 5 splits in one launch (grid.y = segment)
// ===========================================================================
struct SplitJobs {
    const float* src[5];
    __nv_bfloat16* hi[5];
    __nv_bfloat16* lo[5];
    int n4[5];
};

__global__ __launch_bounds__(256) void split_all(SplitJobs j)
{
    const int seg = blockIdx.y;
    const int i = blockIdx.x * 256 + threadIdx.x;
    if (i < j.n4[seg]) {
        float4 v = ((const float4*)j.src[seg])[i];
        uint2 h, l;
        split4(v, h, l);
        ((uint2*)j.hi[seg])[i] = h;
        ((uint2*)j.lo[seg])[i] = l;
    }
}

// ===========================================================================
// GEMM core (NT): tile M=64 x N=128, BK=64, 256 threads (unchanged from R13).
// ===========================================================================
#define GEMM_STAGE 49152
#define GEMM_SMEM  (2 * GEMM_STAGE)   // 98304

template<bool BF16OUT>
__device__ __forceinline__ void gemm_tile(
    const __nv_bfloat16* __restrict__ Xh, const __nv_bfloat16* __restrict__ Xl,
    const __nv_bfloat16* __restrict__ Wh, const __nv_bfloat16* __restrict__ Wl,
    const float* __restrict__ bias,
    float* __restrict__ Yf, __nv_bfloat16* __restrict__ Yh,
    __nv_bfloat16* __restrict__ Yl, int K, int N, int bm, int bn,
    uint32_t sb)
{
    const int t    = threadIdx.x;
    const int wid  = t >> 5;        // 0..7
    const int lane = t & 31;
    const int wm   = (wid & 1) * 32;
    const int wn   = (wid >> 1) * 32;

    float acc[2][4][4];
#pragma unroll
    for (int i = 0; i < 2; i++)
#pragma unroll
        for (int j = 0; j < 4; j++)
#pragma unroll
            for (int r = 0; r < 4; r++) acc[i][j][r] = 0.0f;

    const int a_row = (lane & 15);
    const int a_kb  = ((lane >> 4) & 1) * 16;
    const int b_row = ((lane >> 4) & 1) * 8 + (lane & 7);
    const int b_kb  = ((lane >> 3) & 1) * 16;

    const int nchunks = K / 64;

    auto load_stage = [&](int c, int s) {
        const int k0 = c * 64;
        const uint32_t st = sb + s * GEMM_STAGE;
#pragma unroll
        for (int i = 0; i < 2; ++i) {
            const int f   = t + 256 * i;
            const int row = f >> 3;
            const int ch  = (f & 7) * 8;
            const uint32_t off = SWZ128((uint32_t)(row * 128 + ch * 2));
            const size_t xo = (size_t)(bm + row) * K + k0 + ch;
            cp_async16(st + off,        &Xh[xo]);
            cp_async16(st + 8192 + off, &Xl[xo]);
        }
#pragma unroll
        for (int i = 0; i < 4; ++i) {
            const int f   = t + 256 * i;
            const int row = f >> 3;
            const int ch  = (f & 7) * 8;
            const uint32_t off = SWZ128((uint32_t)(row * 128 + ch * 2));
            const size_t wo = (size_t)(bn + row) * K + k0 + ch;
            cp_async16(st + 16384 + off, &Wh[wo]);
            cp_async16(st + 32768 + off, &Wl[wo]);
        }
        CP_COMMIT();
    };

    load_stage(0, 0);
    for (int c = 0; c < nchunks; ++c) {
        if (c + 1 < nchunks) { load_stage(c + 1, (c + 1) & 1); CP_WAIT(1); }
        else                 { CP_WAIT(0); }
        __syncthreads();

        const uint32_t st  = sb + (c & 1) * GEMM_STAGE;
        const uint32_t sAh = st, sAl = st + 8192, sBh = st + 16384, sBl = st + 32768;
#pragma unroll
        for (int ks = 0; ks < 4; ++ks) {
            const int kb = ks * 32;
            uint32_t bh[4][2], bl[4][2];
#pragma unroll
            for (int np = 0; np < 2; ++np) {
                const uint32_t boff =
                    SWZ128((uint32_t)((wn + np * 16 + b_row) * 128 + kb + b_kb));
                uint32_t r4[4];
                ldsm_x4(sBh + boff, r4);
                bh[2 * np][0] = r4[0]; bh[2 * np][1] = r4[1];
                bh[2 * np + 1][0] = r4[2]; bh[2 * np + 1][1] = r4[3];
                ldsm_x4(sBl + boff, r4);
                bl[2 * np][0] = r4[0]; bl[2 * np][1] = r4[1];
                bl[2 * np + 1][0] = r4[2]; bl[2 * np + 1][1] = r4[3];
            }
#pragma unroll
            for (int mt = 0; mt < 2; ++mt) {
                const uint32_t aoff =
                    SWZ128((uint32_t)((wm + mt * 16 + a_row) * 128 + kb + a_kb));
                uint32_t ah[4], al[4];
                ldsm_x4(sAh + aoff, ah);
                ldsm_x4(sAl + aoff, al);
#pragma unroll
                for (int nt = 0; nt < 4; ++nt) mma16816(acc[mt][nt], ah, bh[nt]);
#pragma unroll
                for (int nt = 0; nt < 4; ++nt) mma16816(acc[mt][nt], ah, bl[nt]);
#pragma unroll
                for (int nt = 0; nt < 4; ++nt) mma16816(acc[mt][nt], al, bh[nt]);
            }
        }
        __syncthreads();
    }

    const int cr = lane >> 2;
    const int cc = (lane & 3) * 2;
#pragma unroll
    for (int mt = 0; mt < 2; ++mt) {
        const int row0 = bm + wm + mt * 16 + cr;
#pragma unroll
        for (int nt = 0; nt < 4; ++nt) {
            const int col = bn + wn + nt * 8 + cc;
            const float2 bv = *(const float2*)&bias[col];
            float a0 = acc[mt][nt][0] + bv.x, a1 = acc[mt][nt][1] + bv.y;
            float a2 = acc[mt][nt][2] + bv.x, a3 = acc[mt][nt][3] + bv.y;
            if (BF16OUT) {
                uint32_t h0, l0, h1, l1;
                split2(a0, a1, h0, l0);
                split2(a2, a3, h1, l1);
                *(uint32_t*)&Yh[(size_t)row0 * N + col]       = h0;
                *(uint32_t*)&Yl[(size_t)row0 * N + col]       = l0;
                *(uint32_t*)&Yh[(size_t)(row0 + 8) * N + col] = h1;
                *(uint32_t*)&Yl[(size_t)(row0 + 8) * N + col] = l1;
            } else {
                float2 v0 = {a0, a1}, v1 = {a2, a3};
                *(float2*)&Yf[(size_t)row0 * N + col]       = v0;
                *(float2*)&Yf[(size_t)(row0 + 8) * N + col] = v1;
            }
        }
    }
}

#define MT64  (MTOT / 64)        // 64
#define NT128 (E_ / 128)         // 8
#define QKV_TILES (3 * MT64 * NT128)   // 1536
#define OUT_TILES (MT64 * NT128)       // 512

struct QkvPtrs {
    const __nv_bfloat16* xh[3];
    const __nv_bfloat16* xl[3];
    __nv_bfloat16* yh[3];
    __nv_bfloat16* yl[3];
    const __nv_bfloat16* wh;
    const __nv_bfloat16* wl;
    const float* bias;
};

__global__ __launch_bounds__(256, 2) void gemm_qkv(QkvPtrs p)
{
    extern __shared__ char smem[];
    const uint32_t sb = smem_u32(smem);
    for (int tile = blockIdx.x; tile < QKV_TILES; tile += gridDim.x) {
        const int z  = tile / (MT64 * NT128);
        const int r  = tile % (MT64 * NT128);
        const int bm = (r / NT128) * 64;
        const int bn = (r % NT128) * 128;
        gemm_tile<true>(p.xh[z], p.xl[z],
                        p.wh + (size_t)z * E_ * E_, p.wl + (size_t)z * E_ * E_,
                        p.bias + z * E_,
                        nullptr, p.yh[z], p.yl[z], E_, E_, bm, bn, sb);
        __syncthreads();
    }
}

__global__ __launch_bounds__(256, 2) void gemm_out(
    const __nv_bfloat16* __restrict__ Xh, const __nv_bfloat16* __restrict__ Xl,
    const __nv_bfloat16* __restrict__ Wh, const __nv_bfloat16* __restrict__ Wl,
    const float* __restrict__ bias, float* __restrict__ Yf)
{
    extern __shared__ char smem[];
    const uint32_t sb = smem_u32(smem);
    for (int tile = blockIdx.x; tile < OUT_TILES; tile += gridDim.x) {
        const int bm = (tile / NT128) * 64;
        const int bn = (tile % NT128) * 128;
        gemm_tile<false>(Xh, Xl, Wh, Wl, bias, Yf, nullptr, nullptr,
                         E_, E_, bm, bn, sb);
        __syncthreads();
    }
}

// ===========================================================================
// Flash attention, SPLIT-KV: grid.z = b*2 + half; each CTA covers 1024 keys.
// Writes unnormalized fp32 partial O + per-row (m, l). 128 thr / 64 q-rows.
// ===========================================================================
#define FA_SMEM (2 * 32768)

__global__ __launch_bounds__(128, 3) void flash_half(
    const __nv_bfloat16* __restrict__ Qh, const __nv_bfloat16* __restrict__ Ql,
    const __nv_bfloat16* __restrict__ Kh, const __nv_bfloat16* __restrict__ Kl,
    const __nv_bfloat16* __restrict__ Vh, const __nv_bfloat16* __restrict__ Vl,
    float* __restrict__ po, float* __restrict__ pm, float* __restrict__ pl)
{
    extern __shared__ char smem[];
    const uint32_t sb = smem_u32(smem);

    const int t    = threadIdx.x;
    const int wid  = t >> 5;
    const int lane = t & 31;
    const int q0   = blockIdx.x * 64;
    const int h    = blockIdx.y;
    const int b    = blockIdx.z >> 1;
    const int half = blockIdx.z & 1;
    const float scale = 0.125f;

    const size_t base = (size_t)b * S_ * E_ + (size_t)h * D_;

    const int qrow = q0 + wid * 16 + (lane >> 2);
    const int qcol = (lane & 3) * 2;
    uint32_t qh[4][4], ql[4][4];
#pragma unroll
    for (int ks = 0; ks < 4; ++ks) {
        const size_t o00 = base + (size_t)qrow * E_ + ks * 16 + qcol;
        qh[ks][0] = *(const uint32_t*)&Qh[o00];
        qh[ks][1] = *(const uint32_t*)&Qh[o00 + 8 * E_];
        qh[ks][2] = *(const uint32_t*)&Qh[o00 + 8];
        qh[ks][3] = *(const uint32_t*)&Qh[o00 + 8 * E_ + 8];
        ql[ks][0] = *(const uint32_t*)&Ql[o00];
        ql[ks][1] = *(const uint32_t*)&Ql[o00 + 8 * E_];
        ql[ks][2] = *(const uint32_t*)&Ql[o00 + 8];
        ql[ks][3] = *(const uint32_t*)&Ql[o00 + 8 * E_ + 8];
    }

    const int b_row = ((lane >> 4) & 1) * 8 + (lane & 7);
    const int b_kb  = ((lane >> 3) & 1) * 16;
    const int v_row = ((lane >> 3) & 1) * 8 + (lane & 7);
    const int v_db  = ((lane >> 4) & 1) * 16;

    float m0 = -INFINITY, m1 = -INFINITY, l0 = 0.0f, l1 = 0.0f;
    float oa[8][4];
#pragma unroll
    for (int nt = 0; nt < 8; ++nt)
#pragma unroll
        for (int r = 0; r < 4; ++r) oa[nt][r] = 0.0f;

    auto load_stage = [&](int kt, int s) {
        const uint32_t st = sb + s * 32768;
#pragma unroll
        for (int i = 0; i < 4; ++i) {
            const int f   = t + 128 * i;
            const int row = f >> 3;
            const int ch  = (f & 7) * 8;
            const uint32_t off = SWZ128((uint32_t)(row * 128 + ch * 2));
            const size_t go = base + (size_t)(kt + row) * E_ + ch;
            cp_async16(st + off,         &Kh[go]);
            cp_async16(st + 8192 + off,  &Kl[go]);
            cp_async16(st + 16384 + off, &Vh[go]);
            cp_async16(st + 24576 + off, &Vl[go]);
        }
        CP_COMMIT();
    };

    const int kt0   = half * (S_ / 2);
    const int niter = (S_ / 2) / 64;   // 16
    load_stage(kt0, 0);
    for (int it = 0; it < niter; ++it) {
        if (it + 1 < niter) { load_stage(kt0 + (it + 1) * 64, (it + 1) & 1); CP_WAIT(1); }
        else                { CP_WAIT(0); }
        __syncthreads();

        const uint32_t st  = sb + (it & 1) * 32768;
        const uint32_t sKh = st, sKl = st + 8192, sVh = st + 16384, sVl = st + 24576;

        float s[8][4];
#pragma unroll
        for (int nt = 0; nt < 8; ++nt)
#pragma unroll
            for (int r = 0; r < 4; ++r) s[nt][r] = 0.0f;

#pragma unroll
        for (int ks = 0; ks < 4; ++ks) {
            uint32_t bh[8][2], bl[8][2];
#pragma unroll
            for (int np = 0; np < 4; ++np) {
                const uint32_t boff =
                    SWZ128((uint32_t)((np * 16 + b_row) * 128 + ks * 32 + b_kb));
                uint32_t r4[4];
                ldsm_x4(sKh + boff, r4);
                bh[2 * np][0] = r4[0]; bh[2 * np][1] = r4[1];
                bh[2 * np + 1][0] = r4[2]; bh[2 * np + 1][1] = r4[3];
                ldsm_x4(sKl + boff, r4);
                bl[2 * np][0] = r4[0]; bl[2 * np][1] = r4[1];
                bl[2 * np + 1][0] = r4[2]; bl[2 * np + 1][1] = r4[3];
            }
#pragma unroll
            for (int nt = 0; nt < 8; ++nt) mma16816(s[nt], qh[ks], bh[nt]);
#pragma unroll
            for (int nt = 0; nt < 8; ++nt) mma16816(s[nt], qh[ks], bl[nt]);
#pragma unroll
            for (int nt = 0; nt < 8; ++nt) mma16816(s[nt], ql[ks], bh[nt]);
        }

#pragma unroll
        for (int nt = 0; nt < 8; ++nt)
#pragma unroll
            for (int r = 0; r < 4; ++r) s[nt][r] *= scale;

        float mx0 = -INFINITY, mx1 = -INFINITY;
#pragma unroll
        for (int nt = 0; nt < 8; ++nt) {
            mx0 = fmaxf(mx0, fmaxf(s[nt][0], s[nt][1]));
            mx1 = fmaxf(mx1, fmaxf(s[nt][2], s[nt][3]));
        }
        mx0 = fmaxf(mx0, __shfl_xor_sync(0xffffffffu, mx0, 1));
        mx0 = fmaxf(mx0, __shfl_xor_sync(0xffffffffu, mx0, 2));
        mx1 = fmaxf(mx1, __shfl_xor_sync(0xffffffffu, mx1, 1));
        mx1 = fmaxf(mx1, __shfl_xor_sync(0xffffffffu, mx1, 2));

        const float mn0 = fmaxf(m0, mx0);
        const float mn1 = fmaxf(m1, mx1);
        const float al0 = __expf(m0 - mn0);
        const float al1 = __expf(m1 - mn1);

        float rs0 = 0.0f, rs1 = 0.0f;
#pragma unroll
        for (int nt = 0; nt < 8; ++nt) {
            float p0 = __expf(s[nt][0] - mn0);
            float p1 = __expf(s[nt][1] - mn0);
            float p2 = __expf(s[nt][2] - mn1);
            float p3 = __expf(s[nt][3] - mn1);
            s[nt][0] = p0; s[nt][1] = p1; s[nt][2] = p2; s[nt][3] = p3;
            rs0 += p0 + p1;
            rs1 += p2 + p3;
        }
        rs0 += __shfl_xor_sync(0xffffffffu, rs0, 1);
        rs0 += __shfl_xor_sync(0xffffffffu, rs0, 2);
        rs1 += __shfl_xor_sync(0xffffffffu, rs1, 1);
        rs1 += __shfl_xor_sync(0xffffffffu, rs1, 2);

        l0 = l0 * al0 + rs0;  m0 = mn0;
        l1 = l1 * al1 + rs1;  m1 = mn1;
#pragma unroll
        for (int nt = 0; nt < 8; ++nt) {
            oa[nt][0] *= al0; oa[nt][1] *= al0;
            oa[nt][2] *= al1; oa[nt][3] *= al1;
        }

#pragma unroll
        for (int ks = 0; ks < 4; ++ks) {
            uint32_t pah[4], pal[4];
            split2(s[2 * ks][0],     s[2 * ks][1],     pah[0], pal[0]);
            split2(s[2 * ks][2],     s[2 * ks][3],     pah[1], pal[1]);
            split2(s[2 * ks + 1][0], s[2 * ks + 1][1], pah[2], pal[2]);
            split2(s[2 * ks + 1][2], s[2 * ks + 1][3], pah[3], pal[3]);

            uint32_t vh[8][2], vl[8][2];
#pragma unroll
            for (int dp = 0; dp < 4; ++dp) {
                const uint32_t voff =
                    SWZ128((uint32_t)((ks * 16 + v_row) * 128 + dp * 32 + v_db));
                uint32_t r4[4];
                ldsm_x4_t(sVh + voff, r4);
                vh[2 * dp][0] = r4[0]; vh[2 * dp][1] = r4[1];
                vh[2 * dp + 1][0] = r4[2]; vh[2 * dp + 1][1] = r4[3];
                ldsm_x4_t(sVl + voff, r4);
                vl[2 * dp][0] = r4[0]; vl[2 * dp][1] = r4[1];
                vl[2 * dp + 1][0] = r4[2]; vl[2 * dp + 1][1] = r4[3];
            }
#pragma unroll
            for (int nt = 0; nt < 8; ++nt) mma16816(oa[nt], pah, vh[nt]);
#pragma unroll
            for (int nt = 0; nt < 8; ++nt) mma16816(oa[nt], pah, vl[nt]);
#pragma unroll
            for (int nt = 0; nt < 8; ++nt) mma16816(oa[nt], pal, vh[nt]);
        }
        __syncthreads();
    }

    // ---- partial epilogue: unnormalized fp32 O + (m, l) per row ----
    const int srow0 = q0 + wid * 16 + (lane >> 2);
    const size_t prow0 = (size_t)half * ROWS_TOT + ((size_t)(b * H_ + h) * S_ + srow0);
    const size_t prow1 = prow0 + 8;
#pragma unroll
    for (int nt = 0; nt < 8; ++nt) {
        const int col = nt * 8 + 2 * (lane & 3);
        float2 v0 = {oa[nt][0], oa[nt][1]};
        float2 v1 = {oa[nt][2], oa[nt][3]};
        *(float2*)&po[prow0 * D_ + col] = v0;
        *(float2*)&po[prow1 * D_ + col] = v1;
    }
    if ((lane & 3) == 0) {
        pm[prow0] = m0; pl[prow0] = l0;
        pm[prow1] = m1; pl[prow1] = l1;
    }
}

// ===========================================================================
// Combine split-KV halves -> normalized split-bf16 attention output
// ===========================================================================
__global__ __launch_bounds__(256) void flash_combine(
    const float* __restrict__ po, const float* __restrict__ pm,
    const float* __restrict__ pl,
    __nv_bfloat16* __restrict__ Oh, __nv_bfloat16* __restrict__ Ol)
{
    const int idx = blockIdx.x * 256 + threadIdx.x;   // over ROWS_TOT*16
    const int row = idx >> 4;
    const int c4  = (idx & 15) * 4;

    const float m1 = pm[row], m2 = pm[row + ROWS_TOT];
    const float l1 = pl[row], l2 = pl[row + ROWS_TOT];
    const float mx = fmaxf(m1, m2);
    const float w1 = __expf(m1 - mx);
    const float w2 = __expf(m2 - mx);
    const float inv = 1.0f / (l1 * w1 + l2 * w2);

    const float4 o1 = *(const float4*)&po[(size_t)row * D_ + c4];
    const float4 o2 = *(const float4*)&po[(size_t)(row + ROWS_TOT) * D_ + c4];
    float vx = (o1.x * w1 + o2.x * w2) * inv;
    float vy = (o1.y * w1 + o2.y * w2) * inv;
    float vz = (o1.z * w1 + o2.z * w2) * inv;
    float vw = (o1.w * w1 + o2.w * w2) * inv;

    // row = (b*H + h)*S + s  ->  dst = (b*S + s)*E + h*64 + c4
    const int s  = row & (S_ - 1);
    const int bh = row >> 11;
    const int h  = bh & (H_ - 1);
    const int b  = bh >> 4;
    const size_t dst = ((size_t)b * S_ + s) * E_ + h * D_ + c4;

    uint32_t h0, lo0, h1, lo1;
    split2(vx, vy, h0, lo0);
    split2(vz, vw, h1, lo1);
    *(uint32_t*)&Oh[dst]     = h0;
    *(uint32_t*)&Ol[dst]     = lo0;
    *(uint32_t*)&Oh[dst + 2] = h1;
    *(uint32_t*)&Ol[dst + 2] = lo1;
}

// ---------------------------------------------------------------------------
// Launch
// ---------------------------------------------------------------------------
extern "C" void kernel_launch(void* const* d_in, const int* in_sizes, int n_in,
                              void* d_out, int out_size)
{
    (void)in_sizes; (void)n_in; (void)out_size;

    const float* q     = (const float*)d_in[0];
    const float* k     = (const float*)d_in[1];
    const float* v     = (const float*)d_in[2];
    const float* w_in  = (const float*)d_in[3];
    const float* b_in  = (const float*)d_in[4];
    const float* w_out = (const float*)d_in[5];
    const float* b_out = (const float*)d_in[6];
    float* out = (float*)d_out;

    __nv_bfloat16 *inq_h, *inq_l, *ink_h, *ink_l, *inv_h, *inv_l;
    __nv_bfloat16 *win_h, *win_l, *wout_h, *wout_l;
    __nv_bfloat16 *pq_h, *pq_l, *pk_h, *pk_l, *pv_h, *pv_l, *at_h, *at_l;
    float *po, *pm, *pl;
    cudaGetSymbolAddress((void**)&inq_h, g_inq_h);  cudaGetSymbolAddress((void**)&inq_l, g_inq_l);
    cudaGetSymbolAddress((void**)&ink_h, g_ink_h);  cudaGetSymbolAddress((void**)&ink_l, g_ink_l);
    cudaGetSymbolAddress((void**)&inv_h, g_inv_h);  cudaGetSymbolAddress((void**)&inv_l, g_inv_l);
    cudaGetSymbolAddress((void**)&win_h, g_win_h);  cudaGetSymbolAddress((void**)&win_l, g_win_l);
    cudaGetSymbolAddress((void**)&wout_h, g_wout_h); cudaGetSymbolAddress((void**)&wout_l, g_wout_l);
    cudaGetSymbolAddress((void**)&pq_h, g_pq_h);    cudaGetSymbolAddress((void**)&pq_l, g_pq_l);
    cudaGetSymbolAddress((void**)&pk_h, g_pk_h);    cudaGetSymbolAddress((void**)&pk_l, g_pk_l);
    cudaGetSymbolAddress((void**)&pv_h, g_pv_h);    cudaGetSymbolAddress((void**)&pv_l, g_pv_l);
    cudaGetSymbolAddress((void**)&at_h, g_at_h);    cudaGetSymbolAddress((void**)&at_l, g_at_l);
    cudaGetSymbolAddress((void**)&po, g_po);
    cudaGetSymbolAddress((void**)&pm, g_pm);
    cudaGetSymbolAddress((void**)&pl, g_pl);

    cudaFuncSetAttribute(gemm_qkv,
                         cudaFuncAttributeMaxDynamicSharedMemorySize, GEMM_SMEM);
    cudaFuncSetAttribute(gemm_out,
                         cudaFuncAttributeMaxDynamicSharedMemorySize, GEMM_SMEM);
    cudaFuncSetAttribute(flash_half,
                         cudaFuncAttributeMaxDynamicSharedMemorySize, FA_SMEM);

    // ---- prepack (single launch, 5 segments) ----
    const int n4_io = MTOT * E_ / 4;
    const int n4_wi = 3 * E_ * E_ / 4;
    const int n4_wo = E_ * E_ / 4;
    SplitJobs sj;
    sj.src[0] = q;     sj.hi[0] = inq_h;  sj.lo[0] = inq_l;  sj.n4[0] = n4_io;
    sj.src[1] = k;     sj.hi[1] = ink_h;  sj.lo[1] = ink_l;  sj.n4[1] = n4_io;
    sj.src[2] = v;     sj.hi[2] = inv_h;  sj.lo[2] = inv_l;  sj.n4[2] = n4_io;
    sj.src[3] = w_in;  sj.hi[3] = win_h;  sj.lo[3] = win_l;  sj.n4[3] = n4_wi;
    sj.src[4] = w_out; sj.hi[4] = wout_h; sj.lo[4] = wout_l; sj.n4[4] = n4_wo;
    split_all<<<dim3(n4_io / 256, 5), 256>>>(sj);

    // ---- QKV projections (persistent) ----
    QkvPtrs qp;
    qp.xh[0] = inq_h; qp.xl[0] = inq_l; qp.yh[0] = pq_h; qp.yl[0] = pq_l;
    qp.xh[1] = ink_h; qp.xl[1] = ink_l; qp.yh[1] = pk_h; qp.yl[1] = pk_l;
    qp.xh[2] = inv_h; qp.xl[2] = inv_l; qp.yh[2] = pv_h; qp.yl[2] = pv_l;
    qp.wh = win_h; qp.wl = win_l; qp.bias = b_in;
    gemm_qkv<<<296, 256, GEMM_SMEM>>>(qp);

    // ---- attention: split-KV halves + combine ----
    flash_half<<<dim3(S_ / 64, H_, B_ * 2), 128, FA_SMEM>>>(
        pq_h, pq_l, pk_h, pk_l, pv_h, pv_l, po, pm, pl);
    flash_combine<<<(ROWS_TOT * 16) / 256, 256>>>(po, pm, pl, at_h, at_l);

    // ---- out projection (persistent) ----
    gemm_out<<<296, 256, GEMM_SMEM>>>(
        at_h, at_l, wout_h, wout_l, b_out, out);
}